// round 10
// baseline (speedup 1.0000x reference)
#include <cuda_runtime.h>

#define PN 4
#define LN 512
#define DN 64
typedef unsigned long long ull;

// ---------------- device scratch ----------------
__device__ __align__(16) float g_rps[PN * LN * 4];  // row partial sums (4 kb)
__device__ __align__(16) float g_cps[PN * LN * 8];  // col partial sums (8 jb)
__device__ __align__(16) float g_pn[128];
__device__ __align__(16) float g_pd[128];
__device__ volatile unsigned g_bar0;                // zero-init; winner resets
__device__ unsigned g_tick;

__device__ __forceinline__ ull add2(ull a, ull b) {
    ull r; asm("add.rn.f32x2 %0, %1, %2;" : "=l"(r) : "l"(a), "l"(b)); return r;
}

// ============ single persistent kernel: 128 blocks, 512 thr, 64j x 128k ======
// smem: z0d [64 d][132]  dup pairs (aj,aj), pitch 132 (16B-aligned rows)
//       z1n [64 d][128]  = -z1, natural k order
// Warp owns a j-quad: a-loads are 2x LDS.128 warp-broadcast; b-load is one
// conflict-free LDS.128. Mainloop is 2-stage software-pipelined: d+1's loads
// issue before d's compute, hiding the 29-cyc LDS latency.
__global__ __launch_bounds__(512, 1) void k_all(const float* __restrict__ z,
                                                const float* __restrict__ wgt,
                                                const float* __restrict__ bias,
                                                float* __restrict__ out) {
    extern __shared__ float smd[];
    float* z0d = smd;                 // 64*132 floats
    float* z1n = smd + 64 * 132;      // 64*128 floats
    __shared__ float scs[16][128];
    __shared__ float sA[64], sB[128];
    __shared__ float sn[16], sd[16];
    __shared__ int   s_win;

    const int kb = blockIdx.x, jb = blockIdx.y, p = blockIdx.z;
    const int bid = kb + 4 * jb + 32 * p;       // 0..127
    const int t  = threadIdx.x;
    const int j0 = jb * 64, k0 = kb * 128;
    const int tx = t & 31, ty = t >> 5;         // lane = k-quad, warp = j-quad

    const float4* z0g = (const float4*)(z + ((size_t)p * LN + j0) * DN);
    const float4* z1g = (const float4*)(z + ((size_t)(p + PN) * LN + k0) * DN);

    // ---- prologue: z0 -> dup pairs (warp-uniform dq, lane = row) ----
    #pragma unroll
    for (int i = 0; i < 2; i++) {
        int r  = tx + 32 * i;                   // j row 0..63
        int dq = ty;                            // d quad 0..15
        float4 v = z0g[r * 16 + dq];
        *(float2*)(z0d + (4 * dq + 0) * 132 + 2 * r) = make_float2(v.x, v.x);
        *(float2*)(z0d + (4 * dq + 1) * 132 + 2 * r) = make_float2(v.y, v.y);
        *(float2*)(z0d + (4 * dq + 2) * 132 + 2 * r) = make_float2(v.z, v.z);
        *(float2*)(z0d + (4 * dq + 3) * 132 + 2 * r) = make_float2(v.w, v.w);
    }
    // ---- prologue: z1 -> negated natural (conflict-free STS.32) ----
    #pragma unroll
    for (int i = 0; i < 4; i++) {
        int r  = tx + 32 * i;                   // k row 0..127
        int dq = ty;
        float4 u = z1g[r * 16 + dq];
        z1n[(4 * dq + 0) * 128 + r] = -u.x;
        z1n[(4 * dq + 1) * 128 + r] = -u.y;
        z1n[(4 * dq + 2) * 128 + r] = -u.z;
        z1n[(4 * dq + 3) * 128 + r] = -u.w;
    }
    __syncthreads();

    // ---- mainloop: j = 4*ty..+3, k = 4*tx..+3, acc = sum_d |a-b| >= 0 ----
    ull acc[8];                                  // [jj][kp]
    #pragma unroll
    for (int q = 0; q < 8; q++) acc[q] = 0;

    const float* z0b = z0d + 8 * ty;
    const float* z1b = z1n + 4 * tx;

    // stage-0 prefetch
    ulonglong2 aPc = *(const ulonglong2*)(z0b);
    ulonglong2 aQc = *(const ulonglong2*)(z0b + 4);
    ulonglong2 bvc = *(const ulonglong2*)(z1b);

    #pragma unroll 4
    for (int d = 0; d < DN; d++) {
        int dn = (d + 1) & 63;                   // wrap: last prefetch harmless
        ulonglong2 aPn = *(const ulonglong2*)(z0b + dn * 132);
        ulonglong2 aQn = *(const ulonglong2*)(z0b + dn * 132 + 4);
        ulonglong2 bvn = *(const ulonglong2*)(z1b + dn * 128);

        ull ap[4] = { aPc.x, aPc.y, aQc.x, aQc.y };
        ull bp0 = bvc.x, bp1 = bvc.y;            // (-bk0,-bk1) (-bk2,-bk3)
        #pragma unroll
        for (int jj = 0; jj < 4; jj++) {
            ull d0 = add2(ap[jj], bp0) & 0x7fffffff7fffffffULL;
            ull d1 = add2(ap[jj], bp1) & 0x7fffffff7fffffffULL;
            acc[jj * 2 + 0] = add2(acc[jj * 2 + 0], d0);
            acc[jj * 2 + 1] = add2(acc[jj * 2 + 1], d1);
        }
        aPc = aPn; aQc = aQn; bvc = bvn;
    }

    // ---- epilogue: E = exp(-acc); negations folded into modifiers ----
    float va[4][4], E[4][4];
    #pragma unroll
    for (int jj = 0; jj < 4; jj++) {
        float2 v0 = *(float2*)&acc[jj * 2 + 0];
        float2 v1 = *(float2*)&acc[jj * 2 + 1];
        va[jj][0] = v0.x; va[jj][1] = v0.y; va[jj][2] = v1.x; va[jj][3] = v1.y;
        #pragma unroll
        for (int i = 0; i < 4; i++) E[jj][i] = __expf(-va[jj][i]);
    }

    // ---- row partial sums (this block's 128 k = full warp) ----
    #pragma unroll
    for (int jj = 0; jj < 4; jj++) {
        float e = (E[jj][0] + E[jj][1]) + (E[jj][2] + E[jj][3]);
        #pragma unroll
        for (int o = 16; o; o >>= 1) e += __shfl_xor_sync(~0u, e, o);
        if (tx == 0)
            g_rps[((size_t)p * LN + j0 + 4 * ty + jj) * 4 + kb] = e;
    }

    // ---- col partial sums (64 j = 16 warps) ----
    {
        float c0 = 0, c1 = 0, c2 = 0, c3 = 0;
        #pragma unroll
        for (int jj = 0; jj < 4; jj++) {
            c0 += E[jj][0]; c1 += E[jj][1]; c2 += E[jj][2]; c3 += E[jj][3];
        }
        *(float4*)&scs[ty][4 * tx] = make_float4(c0, c1, c2, c3);
    }
    __syncthreads();
    if (t < 128) {
        float e = 0.f;
        #pragma unroll
        for (int q = 0; q < 16; q++) e += scs[q][t];
        g_cps[((size_t)p * LN + k0 + t) * 8 + jb] = e;
    }

    // ---- grid barrier (128 co-resident blocks) ----
    __threadfence();
    __syncthreads();
    if (t == 0) {
        atomicAdd((unsigned*)&g_bar0, 1u);
        while (g_bar0 < 128u) { }
    }
    __syncthreads();

    // ---- per-block A (64 j) and B (128 k) from partials ----
    if (t < 64) {
        float4 u = __ldcg((const float4*)(g_rps + ((size_t)p * LN + j0 + t) * 4));
        sA[t] = 1.0f / ((u.x + u.y) + (u.z + u.w));
    } else if (t < 192) {
        int id = t - 64;
        const float4* q = (const float4*)(g_cps + ((size_t)p * LN + k0 + id) * 8);
        float4 u = __ldcg(q), v = __ldcg(q + 1);
        sB[id] = 1.0f / (((u.x + u.y) + (u.z + u.w)) + ((v.x + v.y) + (v.z + v.w)));
    }
    __syncthreads();

    // ---- phase C: own-tile sum(c*s), sum(c); s = -va ----
    {
        float4 Bv = *(const float4*)&sB[4 * tx];
        const float Bk[4] = { Bv.x, Bv.y, Bv.z, Bv.w };
        float num = 0.f, den = 0.f;
        #pragma unroll
        for (int jj = 0; jj < 4; jj++) {
            float Aj = sA[4 * ty + jj];          // broadcast
            #pragma unroll
            for (int i = 0; i < 4; i++) {
                float a = E[jj][i] * Aj;
                float b = E[jj][i] * Bk[i];
                float c = a + b - a * b;
                num = fmaf(c, -va[jj][i], num);  // negation via modifier
                den += c;
            }
        }
        #pragma unroll
        for (int o = 16; o; o >>= 1) {
            num += __shfl_xor_sync(~0u, num, o);
            den += __shfl_xor_sync(~0u, den, o);
        }
        if (tx == 0) { sn[ty] = num; sd[ty] = den; }
        __syncthreads();
        if (t == 0) {
            float N = 0.f, D = 0.f;
            #pragma unroll
            for (int q = 0; q < 16; q++) { N += sn[q]; D += sd[q]; }
            g_pn[bid] = N; g_pd[bid] = D;
        }
    }

    // ---- ticket: last block finalizes ----
    __threadfence();
    __syncthreads();
    if (t == 0) s_win = (atomicAdd(&g_tick, 1u) == 127u) ? 1 : 0;
    __syncthreads();
    if (!s_win) return;

    if (t < 128) {                               // warp w == pair p
        float N = __ldcg(&g_pn[t]), D = __ldcg(&g_pd[t]);
        #pragma unroll
        for (int o = 16; o; o >>= 1) {
            N += __shfl_xor_sync(~0u, N, o);
            D += __shfl_xor_sync(~0u, D, o);
        }
        if ((t & 31) == 0) {
            float cv = N / D;
            int pp = t >> 5;
            #pragma unroll
            for (int c = 0; c < 4; c++)
                out[pp * 4 + c] = cv * wgt[c] + bias[c];
        }
    }
    if (t == 0) { g_bar0 = 0; g_tick = 0; }      // reset for graph replay
}

// ---------------- launch ----------------
extern "C" void kernel_launch(void* const* d_in, const int* in_sizes, int n_in,
                              void* d_out, int out_size) {
    const float* z = (const float*)d_in[0];   // (8, 512, 64) fp32
    const float* w = (const float*)d_in[1];   // (1, 4)
    const float* b = (const float*)d_in[2];   // (4,)
    float* out = (float*)d_out;               // (4, 4)

    const int smem = (132 + 128) * 64 * 4;    // 66560 B dynamic
    cudaFuncSetAttribute(k_all, cudaFuncAttributeMaxDynamicSharedMemorySize, smem);
    k_all<<<dim3(4, 8, 4), 512, smem>>>(z, w, b, out);
}

// round 11
// speedup vs baseline: 1.1366x; 1.1366x over previous
#include <cuda_runtime.h>

#define PN 4
#define LN 512
#define DN 64

// ---------------- device scratch ----------------
__device__ __align__(16) float g_rps[PN * LN * 4];  // row partial sums (4 kb)
__device__ __align__(16) float g_cps[PN * LN * 8];  // col partial sums (8 jb)
__device__ __align__(16) float g_pn[128];
__device__ __align__(16) float g_pd[128];
__device__ volatile unsigned g_bar0;                // zero-init; winner resets
__device__ unsigned g_tick;

// ============ single persistent kernel: 128 blocks, 512 thr, 64j x 128k ======
// Min-identity: s = 2*sum_d min(a,b) - SA_j - SB_k.  Inner loop per element is
// 1 FMNMX (alu pipe) + 1 FADD (fma pipe): balanced dual-pipe, half the fma load
// of the |a-b| form.  a-loads are warp-broadcast LDS.128; b-load conflict-free.
__global__ __launch_bounds__(512, 1) void k_all(const float* __restrict__ z,
                                                const float* __restrict__ wgt,
                                                const float* __restrict__ bias,
                                                float* __restrict__ out) {
    extern __shared__ float smd[];
    float* z0s = smd;                 // [64 d][68]  z0 tile, natural
    float* z1s = smd + 64 * 68;       // [64 d][132] z1 tile, natural
    __shared__ float part0[16][65];   // z0 d-quad row sums
    __shared__ float part1[16][129];  // z1 d-quad row sums
    __shared__ float sSA[64], sSB[128];
    __shared__ float scs[16][128];
    __shared__ float sAi[64], sBi[128];
    __shared__ float sn[16], sd[16];
    __shared__ int   s_win;

    const int kb = blockIdx.x, jb = blockIdx.y, p = blockIdx.z;
    const int bid = kb + 4 * jb + 32 * p;       // 0..127
    const int t  = threadIdx.x;
    const int j0 = jb * 64, k0 = kb * 128;
    const int tx = t & 31, ty = t >> 5;         // lane, warp (= d-quad in prologue)

    const float4* z0g = (const float4*)(z + ((size_t)p * LN + j0) * DN);
    const float4* z1g = (const float4*)(z + ((size_t)(p + PN) * LN + k0) * DN);

    // ---- prologue: batched LDG, then STS + d-quad row-sum partials ----
    float4 v0[2], v1[4];
    #pragma unroll
    for (int i = 0; i < 2; i++) v0[i] = z0g[(tx + 32 * i) * 16 + ty];
    #pragma unroll
    for (int i = 0; i < 4; i++) v1[i] = z1g[(tx + 32 * i) * 16 + ty];

    #pragma unroll
    for (int i = 0; i < 2; i++) {
        int r = tx + 32 * i;                    // j row
        z0s[(4 * ty + 0) * 68 + r] = v0[i].x;
        z0s[(4 * ty + 1) * 68 + r] = v0[i].y;
        z0s[(4 * ty + 2) * 68 + r] = v0[i].z;
        z0s[(4 * ty + 3) * 68 + r] = v0[i].w;
        part0[ty][r] = (v0[i].x + v0[i].y) + (v0[i].z + v0[i].w);
    }
    #pragma unroll
    for (int i = 0; i < 4; i++) {
        int r = tx + 32 * i;                    // k row
        z1s[(4 * ty + 0) * 132 + r] = v1[i].x;
        z1s[(4 * ty + 1) * 132 + r] = v1[i].y;
        z1s[(4 * ty + 2) * 132 + r] = v1[i].z;
        z1s[(4 * ty + 3) * 132 + r] = v1[i].w;
        part1[ty][r] = (v1[i].x + v1[i].y) + (v1[i].z + v1[i].w);
    }
    __syncthreads();

    // SA_j / SB_k (full d sums) from the 16 d-quad partials
    if (t < 64) {
        float s0 = 0.f;
        #pragma unroll
        for (int q = 0; q < 16; q++) s0 += part0[q][t];
        sSA[t] = s0;
    } else if (t < 192) {
        int id = t - 64;
        float s1 = 0.f;
        #pragma unroll
        for (int q = 0; q < 16; q++) s1 += part1[q][id];
        sSB[id] = s1;
    }

    // ---- mainloop: j = 4*ty..+3, k = 4*tx..+3; acc = sum_d min(a,b) ----
    float acc[4][4];
    #pragma unroll
    for (int jj = 0; jj < 4; jj++)
        #pragma unroll
        for (int i = 0; i < 4; i++) acc[jj][i] = 0.f;

    #pragma unroll 8
    for (int d = 0; d < DN; d++) {
        float4 av = *(const float4*)(z0s + d * 68 + 4 * ty);    // warp-broadcast
        float4 bv = *(const float4*)(z1s + d * 132 + 4 * tx);   // conflict-free
        const float a[4] = { av.x, av.y, av.z, av.w };
        const float b[4] = { bv.x, bv.y, bv.z, bv.w };
        #pragma unroll
        for (int jj = 0; jj < 4; jj++)
            #pragma unroll
            for (int i = 0; i < 4; i++)
                acc[jj][i] += fminf(a[jj], b[i]);   // FMNMX(alu) + FADD(fma)
    }
    __syncthreads();   // sSA/sSB written pre-mainloop by threads 0..191

    // ---- epilogue: s = 2*acc - SA - SB;  E = exp(s) ----
    float s[4][4], E[4][4];
    {
        float4 SAv = *(const float4*)&sSA[4 * ty];
        float4 SBv = *(const float4*)&sSB[4 * tx];
        const float SAj[4] = { SAv.x, SAv.y, SAv.z, SAv.w };
        const float SBk[4] = { SBv.x, SBv.y, SBv.z, SBv.w };
        #pragma unroll
        for (int jj = 0; jj < 4; jj++)
            #pragma unroll
            for (int i = 0; i < 4; i++) {
                float v = fmaf(2.0f, acc[jj][i], -(SAj[jj] + SBk[i]));
                s[jj][i] = v;
                E[jj][i] = __expf(v);
            }
    }

    // ---- row partial sums (this block's 128 k = full warp) ----
    #pragma unroll
    for (int jj = 0; jj < 4; jj++) {
        float e = (E[jj][0] + E[jj][1]) + (E[jj][2] + E[jj][3]);
        #pragma unroll
        for (int o = 16; o; o >>= 1) e += __shfl_xor_sync(~0u, e, o);
        if (tx == 0)
            g_rps[((size_t)p * LN + j0 + 4 * ty + jj) * 4 + kb] = e;
    }

    // ---- col partial sums (64 j = 16 warps) ----
    {
        float c0 = 0, c1 = 0, c2 = 0, c3 = 0;
        #pragma unroll
        for (int jj = 0; jj < 4; jj++) {
            c0 += E[jj][0]; c1 += E[jj][1]; c2 += E[jj][2]; c3 += E[jj][3];
        }
        *(float4*)&scs[ty][4 * tx] = make_float4(c0, c1, c2, c3);
    }
    __syncthreads();
    if (t < 128) {
        float e = 0.f;
        #pragma unroll
        for (int q = 0; q < 16; q++) e += scs[q][t];
        g_cps[((size_t)p * LN + k0 + t) * 8 + jb] = e;
    }

    // ---- grid barrier (128 co-resident blocks) ----
    __threadfence();
    __syncthreads();
    if (t == 0) {
        atomicAdd((unsigned*)&g_bar0, 1u);
        while (g_bar0 < 128u) { }
    }
    __syncthreads();

    // ---- per-block 1/rowsum (64 j) and 1/colsum (128 k) ----
    if (t < 64) {
        float4 u = __ldcg((const float4*)(g_rps + ((size_t)p * LN + j0 + t) * 4));
        sAi[t] = 1.0f / ((u.x + u.y) + (u.z + u.w));
    } else if (t < 192) {
        int id = t - 64;
        const float4* q = (const float4*)(g_cps + ((size_t)p * LN + k0 + id) * 8);
        float4 u = __ldcg(q), v = __ldcg(q + 1);
        sBi[id] = 1.0f / (((u.x + u.y) + (u.z + u.w)) + ((v.x + v.y) + (v.z + v.w)));
    }
    __syncthreads();

    // ---- phase C: own-tile sum(c*s), sum(c) ----
    {
        float4 Bv = *(const float4*)&sBi[4 * tx];
        const float Bk[4] = { Bv.x, Bv.y, Bv.z, Bv.w };
        float num = 0.f, den = 0.f;
        #pragma unroll
        for (int jj = 0; jj < 4; jj++) {
            float Aj = sAi[4 * ty + jj];         // broadcast
            #pragma unroll
            for (int i = 0; i < 4; i++) {
                float a = E[jj][i] * Aj;
                float b = E[jj][i] * Bk[i];
                float c = a + b - a * b;
                num = fmaf(c, s[jj][i], num);
                den += c;
            }
        }
        #pragma unroll
        for (int o = 16; o; o >>= 1) {
            num += __shfl_xor_sync(~0u, num, o);
            den += __shfl_xor_sync(~0u, den, o);
        }
        if (tx == 0) { sn[ty] = num; sd[ty] = den; }
        __syncthreads();
        if (t == 0) {
            float N = 0.f, D = 0.f;
            #pragma unroll
            for (int q = 0; q < 16; q++) { N += sn[q]; D += sd[q]; }
            g_pn[bid] = N; g_pd[bid] = D;
        }
    }

    // ---- ticket: last block finalizes ----
    __threadfence();
    __syncthreads();
    if (t == 0) s_win = (atomicAdd(&g_tick, 1u) == 127u) ? 1 : 0;
    __syncthreads();
    if (!s_win) return;

    if (t < 128) {                               // warp w == pair p
        float N = __ldcg(&g_pn[t]), D = __ldcg(&g_pd[t]);
        #pragma unroll
        for (int o = 16; o; o >>= 1) {
            N += __shfl_xor_sync(~0u, N, o);
            D += __shfl_xor_sync(~0u, D, o);
        }
        if ((t & 31) == 0) {
            float cv = N / D;
            int pp = t >> 5;
            #pragma unroll
            for (int c = 0; c < 4; c++)
                out[pp * 4 + c] = cv * wgt[c] + bias[c];
        }
    }
    if (t == 0) { g_bar0 = 0; g_tick = 0; }      // reset for graph replay
}

// ---------------- launch ----------------
extern "C" void kernel_launch(void* const* d_in, const int* in_sizes, int n_in,
                              void* d_out, int out_size) {
    const float* z = (const float*)d_in[0];   // (8, 512, 64) fp32
    const float* w = (const float*)d_in[1];   // (1, 4)
    const float* b = (const float*)d_in[2];   // (4,)
    float* out = (float*)d_out;               // (4, 4)

    const int smem = (68 + 132) * 64 * 4;     // 51200 B dynamic
    cudaFuncSetAttribute(k_all, cudaFuncAttributeMaxDynamicSharedMemorySize, smem);
    k_all<<<dim3(4, 8, 4), 512, smem>>>(z, w, b, out);
}